// round 16
// baseline (speedup 1.0000x reference)
#include <cuda_runtime.h>
#include <cstdint>

// ---- static config ----
#define BB      16
#define AA      3
#define NC      80
#define WH      76
#define MM      32
#define EE      85                       // 5 + NC
#define CELLS   (WH * WH)                // 5776
#define CPI     (AA * CELLS)             // cells per image: 17328
#define EPI     (CPI * EE)               // elems per image
#define NTOT    (BB * EPI)               // 23,566,080 decoded elements
#define NV4     (NTOT / 4)               // 5,891,520 float4s
#define NGROUPS (NV4 / 680)              // 8664 groups (680 float4 = 32 cells)
#define NCELLS  (BB * CPI)               // 277,248
#define NOOBJ_OFF  NTOT
#define OBJ_OFF    (NTOT + NCELLS)

#define GPB       3                      // groups per block
#define TPB       255                    // 85 * GPB threads
#define CELLS_PB  96                     // 32 * GPB cells per block
#define NB        (NGROUPS / GPB)        // 2888 blocks, exact tiling

__constant__ float c_anchor_w[3] = {10.f / 8.f, 16.f / 8.f, 33.f / 8.f};
__constant__ float c_anchor_h[3] = {13.f / 8.f, 30.f / 8.f, 23.f / 8.f};
__constant__ float c_all_anchors[9][2] = {
    {10.f, 13.f}, {16.f, 30.f}, {33.f, 23.f},
    {30.f, 61.f}, {62.f, 45.f}, {59.f, 119.f},
    {116.f, 90.f}, {156.f, 198.f}, {373.f, 326.f}};

// 3-instruction sigmoid via MUFU.TANH
__device__ __forceinline__ float sigt(float x) {
    float t;
    float h = 0.5f * x;
    asm("tanh.approx.f32 %0, %1;" : "=f"(t) : "f"(h));
    return fmaf(0.5f, t, 0.5f);
}
__device__ __forceinline__ float4 sig4(float4 x) {
    float4 v;
    v.x = sigt(x.x); v.y = sigt(x.y); v.z = sigt(x.z); v.w = sigt(x.w);
    return v;
}

// ------------------------------------------------------------------
// Fully fused: each block OWNS 3 groups = 2040 float4s = 96 cells.
// Phase 1: stream decode (8 float4s/thread, imm offsets, all stored;
//          box lanes temporarily hold sigmoid values). The 7 special-q
//          threads per group also stash raw box-lane floats in smem.
// Phase 2 (after syncthreads): threads 0..95 decode their cell's box
//          from smem, scalar-patch the 4 box elements in `out`
//          (same-block store ordering via the barrier), and compute
//          noobj/obj from smem GT tables. Zero extra global reads.
// ------------------------------------------------------------------
__global__ void __launch_bounds__(TPB) yolo_fused_kernel(
    const float* __restrict__ pred,
    const float* __restrict__ gt,
    float* __restrict__ out) {

    __shared__ float  sbox[CELLS_PB][4];   // raw box lanes per cell
    __shared__ float4 gboxS[2 * MM];       // GT xyxy (2 images for boundary blocks)
    __shared__ float  gAS[2 * MM];
    __shared__ int    sflatS[2 * MM];      // GLOBAL assigned cell or -1

    int bid = blockIdx.x;
    int tid = threadIdx.x;

    int cell0 = CELLS_PB * bid;            // first global cell of this block
    int b0 = cell0 / CPI;
    int b1 = (cell0 + CELLS_PB - 1) / CPI; // may equal b0

    // ---- phase 1a: issue decode loads (front-batched by ptxas) ----
    int gi = tid / 85;                     // group within block (0..2)
    int q  = tid - gi * 85;
    int G  = GPB * bid + gi;               // global group
    int f  = 680 * G + q;                  // base float4

    const float4* pb = (const float4*)pred + f;
    float4*       ob = (float4*)out + f;

    float4 x[8];
#pragma unroll
    for (int k = 0; k < 8; k++)
        x[k] = __ldcs(pb + 85 * k);

    // ---- phase 1b: GT staging + best-anchor (overlaps load latency) ----
    if (tid < 64) {
        int img = (tid < MM) ? b0 : b1;
        int m   = tid & 31;
        const float* g = gt + (size_t)(img * MM + m) * 6;
        float cx = g[1], cy = g[2], gw = g[3], gh = g[4];
        float x1 = (cx - gw * 0.5f) * 608.0f;
        float y1 = (cy - gh * 0.5f) * 608.0f;
        float x2 = (cx + gw * 0.5f) * 608.0f;
        float y2 = (cy + gh * 0.5f) * 608.0f;
        gboxS[tid] = make_float4(x1, y1, x2, y2);
        float garea = (x2 - x1) * (y2 - y1);
        gAS[tid] = garea;

        int   best  = 0;
        float bestv = -1.0f;
#pragma unroll
        for (int k = 0; k < 9; k++) {
            float ow = c_all_anchors[k][0] / 608.0f;
            float oh = c_all_anchors[k][1] / 608.0f;
            float ax1 = (cx - ow * 0.5f) * 608.0f;
            float ay1 = (cy - oh * 0.5f) * 608.0f;
            float ax2 = (cx + ow * 0.5f) * 608.0f;
            float ay2 = (cy + oh * 0.5f) * 608.0f;
            float aar = (ax2 - ax1) * (ay2 - ay1);
            float ix = fmaxf(fminf(x2, ax2) - fmaxf(x1, ax1), 0.0f);
            float iy = fmaxf(fminf(y2, ay2) - fmaxf(y1, ay1), 0.0f);
            float inter = ix * iy;
            float iou = inter / (garea + aar - inter);
            if (iou > bestv) { bestv = iou; best = k; }   // strict >: first max
        }
        if (best < AA) {
            int gix = (int)(cx * (float)WH);
            int gjx = (int)(cy * (float)WH);
            sflatS[tid] = img * CPI + (best * WH + gix) * WH + gjx;
        } else {
            sflatS[tid] = -1;
        }
    }

    // ---- phase 1c: sigmoid + store everything; stash raw box lanes ----
#pragma unroll
    for (int k = 0; k < 8; k++)
        __stcs(ob + 85 * k, sig4(x[k]));

    {
        int cb = 32 * gi;   // first cell of this thread's group (block-local)
        if (q == 0) {
#pragma unroll
            for (int k = 0; k < 8; k++) {
                int cc = cb + 4 * k;
                sbox[cc][0] = x[k].x; sbox[cc][1] = x[k].y;
                sbox[cc][2] = x[k].z; sbox[cc][3] = x[k].w;
            }
        } else if (q == 21) {
#pragma unroll
            for (int k = 0; k < 8; k++) {
                int cc = cb + 4 * k + 1;
                sbox[cc][0] = x[k].y; sbox[cc][1] = x[k].z; sbox[cc][2] = x[k].w;
            }
        } else if (q == 22) {
#pragma unroll
            for (int k = 0; k < 8; k++) sbox[cb + 4 * k + 1][3] = x[k].x;
        } else if (q == 42) {
#pragma unroll
            for (int k = 0; k < 8; k++) {
                int cc = cb + 4 * k + 2;
                sbox[cc][0] = x[k].z; sbox[cc][1] = x[k].w;
            }
        } else if (q == 43) {
#pragma unroll
            for (int k = 0; k < 8; k++) {
                int cc = cb + 4 * k + 2;
                sbox[cc][2] = x[k].x; sbox[cc][3] = x[k].y;
            }
        } else if (q == 63) {
#pragma unroll
            for (int k = 0; k < 8; k++) sbox[cb + 4 * k + 3][0] = x[k].w;
        } else if (q == 64) {
#pragma unroll
            for (int k = 0; k < 8; k++) {
                int cc = cb + 4 * k + 3;
                sbox[cc][1] = x[k].x; sbox[cc][2] = x[k].y; sbox[cc][3] = x[k].z;
            }
        }
    }

    __syncthreads();

    // ---- phase 2: per-cell decode-patch + masks (threads 0..95) ----
    if (tid < CELLS_PB) {
        int gc = cell0 + tid;
        int b  = gc / CPI;
        int sel = (b != b0) ? MM : 0;
        int cl = gc - b * CPI;

        int a  = cl / CELLS;
        int sp = cl - a * CELLS;
        int w  = sp / WH;
        int h  = sp - w * WH;

        float p0 = sbox[tid][0];
        float p1 = sbox[tid][1];
        float p2 = sbox[tid][2];
        float p3 = sbox[tid][3];

        float px = sigt(p0) + (float)h;
        float py = sigt(p1) + (float)w;
        float pw = __expf(p2) * c_anchor_w[a];
        float ph = __expf(p3) * c_anchor_h[a];

        // scalar-patch the box lanes (ordered after phase-1 stores by the barrier)
        int e0 = 85 * gc;
        out[e0 + 0] = px;
        out[e0 + 1] = py;
        out[e0 + 2] = pw;
        out[e0 + 3] = ph;

        float x1 = (px - pw * 0.5f) * 8.0f;
        float y1 = (py - ph * 0.5f) * 8.0f;
        float x2 = (px + pw * 0.5f) * 8.0f;
        float y2 = (py + ph * 0.5f) * 8.0f;
        float pa = (x2 - x1) * (y2 - y1);

        bool anyhi = false;
        bool isobj = false;
#pragma unroll 4
        for (int m = 0; m < MM; m++) {
            float4 gb = gboxS[sel + m];
            float ix = fmaxf(fminf(x2, gb.z) - fmaxf(x1, gb.x), 0.0f);
            float iy = fmaxf(fminf(y2, gb.w) - fmaxf(y1, gb.y), 0.0f);
            float inter = ix * iy;
            anyhi |= (3.0f * inter > pa + gAS[sel + m]);   // iou > 0.5, div-free
            isobj |= (sflatS[sel + m] == gc);
        }

        out[OBJ_OFF + gc]   = isobj ? 1.0f : 0.0f;
        out[NOOBJ_OFF + gc] = (!anyhi && !isobj) ? 1.0f : 0.0f;
    }
}

extern "C" void kernel_launch(void* const* d_in, const int* in_sizes, int n_in,
                              void* d_out, int out_size) {
    const float* pred = (const float*)d_in[0];
    const float* gt   = (const float*)d_in[1];
    float* out = (float*)d_out;

    (void)in_sizes; (void)n_in; (void)out_size;

    yolo_fused_kernel<<<NB, TPB>>>(pred, gt, out);
}